// round 15
// baseline (speedup 1.0000x reference)
#include <cuda_runtime.h>
#include <cuda_bf16.h>
#include <math.h>
#include <cstdint>

#define HEADS   4
#define NTOK    256
#define NWIN    512
#define POSN    961
#define QKSCALE 0.17677669529663689f
#define LOG2E   1.4426950408889634f

// ---------------- scratch ----------------
__device__ unsigned short g_wb[384 * 128];     // bf16 gamma-folded W, [j][k]
__device__ float g_cs[384];
__device__ float g_cb[384];
__device__ float g_pos[HEADS * POSN];          // pre-multiplied by LOG2E

// ---------------- helpers ----------------
__device__ __forceinline__ uint32_t bf2pack(float lo, float hi) {
    uint32_t r; asm("cvt.rn.bf16x2.f32 %0,%1,%2;" : "=r"(r) : "f"(hi), "f"(lo)); return r;
}
__device__ __forceinline__ uint32_t smem_u32(const void* p) {
    uint32_t a;
    asm("{ .reg .u64 t; cvta.to.shared.u64 t, %1; cvt.u32.u64 %0, t; }" : "=r"(a) : "l"(p));
    return a;
}
__device__ __forceinline__ void ldmx4(uint32_t* r, uint32_t addr) {
    asm volatile("ldmatrix.sync.aligned.m8n8.x4.shared.b16 {%0,%1,%2,%3}, [%4];"
        : "=r"(r[0]), "=r"(r[1]), "=r"(r[2]), "=r"(r[3]) : "r"(addr));
}
__device__ __forceinline__ void ldmx4t(uint32_t* r, uint32_t addr) {
    asm volatile("ldmatrix.sync.aligned.m8n8.x4.trans.shared.b16 {%0,%1,%2,%3}, [%4];"
        : "=r"(r[0]), "=r"(r[1]), "=r"(r[2]), "=r"(r[3]) : "r"(addr));
}
__device__ __forceinline__ void mma16816(float* c, const uint32_t* a, const uint32_t* b) {
    asm volatile("mma.sync.aligned.m16n8k16.row.col.f32.bf16.bf16.f32 "
        "{%0,%1,%2,%3},{%4,%5,%6,%7},{%8,%9},{%0,%1,%2,%3};"
        : "+f"(c[0]), "+f"(c[1]), "+f"(c[2]), "+f"(c[3])
        : "r"(a[0]), "r"(a[1]), "r"(a[2]), "r"(a[3]), "r"(b[0]), "r"(b[1]));
}
__device__ __forceinline__ float ex2f(float x) {
    float r; asm("ex2.approx.ftz.f32 %0,%1;" : "=f"(r) : "f"(x)); return r;
}

// ---------------- pos-bias MLP ----------------
__device__ __forceinline__ void ln_relu8(float* a, const float* g, const float* b) {
    float m = 0.f;
#pragma unroll
    for (int u = 0; u < 8; u++) m += a[u];
    m *= 0.125f;
    float v = 0.f;
#pragma unroll
    for (int u = 0; u < 8; u++) { float d = a[u] - m; v += d * d; }
    v *= 0.125f;
    float r = rsqrtf(v + 1e-5f);
#pragma unroll
    for (int u = 0; u < 8; u++) a[u] = fmaxf((a[u] - m) * r * g[u] + b[u], 0.f);
}
__device__ __forceinline__ void fc8(const float* a, float* y, const float* w, const float* b) {
#pragma unroll
    for (int o = 0; o < 8; o++) {
        float s = b[o];
#pragma unroll
        for (int u = 0; u < 8; u++) s += a[u] * w[o * 8 + u];
        y[o] = s;
    }
}

__global__ void prep_pos_kernel(
    const float* __restrict__ pp_w, const float* __restrict__ pp_b,
    const float* __restrict__ l1_g, const float* __restrict__ l1_b,
    const float* __restrict__ f1_w, const float* __restrict__ f1_b,
    const float* __restrict__ l2_g, const float* __restrict__ l2_b,
    const float* __restrict__ f2_w, const float* __restrict__ f2_b,
    const float* __restrict__ l3_g, const float* __restrict__ l3_b,
    const float* __restrict__ f3_w, const float* __restrict__ f3_b)
{
    int p = blockIdx.x * blockDim.x + threadIdx.x;
    if (p >= POSN) return;
    float bh = (float)(p / 31 - 15);
    float bw = (float)(p % 31 - 15);
    float a[8], y[8];
#pragma unroll
    for (int u = 0; u < 8; u++) a[u] = bh * pp_w[2 * u] + bw * pp_w[2 * u + 1] + pp_b[u];
    ln_relu8(a, l1_g, l1_b);
    fc8(a, y, f1_w, f1_b);
    ln_relu8(y, l2_g, l2_b);
    fc8(y, a, f2_w, f2_b);
    ln_relu8(a, l3_g, l3_b);
#pragma unroll
    for (int hh = 0; hh < HEADS; hh++) {
        float s = f3_b[hh];
#pragma unroll
        for (int u = 0; u < 8; u++) s += a[u] * f3_w[hh * 8 + u];
        g_pos[hh * POSN + p] = s * LOG2E;
    }
}

// ---------------- fold LN gamma into W, bf16 ----------------
__global__ void prep_w_kernel(const float* __restrict__ qkv_w, const float* __restrict__ qkv_b,
                              const float* __restrict__ g1, const float* __restrict__ b1)
{
    __shared__ float s1[128], s2[128];
    int j = blockIdx.x;
    int k = threadIdx.x;
    float w = qkv_w[j * 128 + k];
    float wg = w * g1[k];
    __nv_bfloat16 wbh = __float2bfloat16(wg);
    g_wb[j * 128 + k] = *(unsigned short*)&wbh;
    s1[k] = __bfloat162float(wbh);
    s2[k] = w * b1[k];
    __syncthreads();
    for (int o = 64; o > 0; o >>= 1) {
        if (k < o) { s1[k] += s1[k + o]; s2[k] += s2[k + o]; }
        __syncthreads();
    }
    if (k == 0) {
        float cb = s2[0] + qkv_b[j];
        if (j < 128) cb *= QKSCALE * LOG2E;
        g_cs[j] = s1[0];
        g_cb[j] = cb;
    }
}

// ---------------- fused QKV-projection + attention ----------------
// smem layout (bytes):
#define FS_QS    0        // [256][80] bf16 q  (doubles as x-chunk buffer during GEMM1)
#define FS_KS    20480    // [256][80] bf16 k
#define FS_VS    40960    // [256][80] bf16 v
#define FS_WB    61440    // [96][272] bf16 W rows for this head
#define FS_TAB   87552    // paired pos table, 961 float2
#define FS_MEAN  95248    // 256 f32
#define FS_RSTD  96272    // 256 f32
#define FS_CS    97296    // 96 f32
#define FS_CB    97680    // 96 f32
#define FUSED_SMEM 98064

__global__ __launch_bounds__(512, 1) void fused_kernel(const float* __restrict__ x,
                                                       float* __restrict__ out)
{
    extern __shared__ char smc[];
    uint32_t sb = smem_u32(smc);
    float* tab   = (float*)(smc + FS_TAB);
    float* smean = (float*)(smc + FS_MEAN);
    float* srstd = (float*)(smc + FS_RSTD);
    float* scs   = (float*)(smc + FS_CS);
    float* scb   = (float*)(smc + FS_CB);

    int tid = threadIdx.x;
    int wid = tid >> 5, lane = tid & 31;
    int w = blockIdx.x >> 2, h = blockIdx.x & 3;
    int b_ = w >> 8, wh = (w >> 4) & 15, ww = w & 15;

    // ---- prologue: W rows for this head, cs/cb, pos table ----
    {
        const uint4* src = (const uint4*)g_wb;
#pragma unroll
        for (int i = 0; i < 3; i++) {
            int f = i * 512 + tid;             // 1536 uint4
            int j = f >> 4, c = f & 15;
            int jg = (j >> 5) * 128 + h * 32 + (j & 31);
            *(uint4*)(smc + FS_WB + j * 272 + c * 16) = src[jg * 16 + c];
        }
    }
    if (tid < 96) {
        int jg = (tid >> 5) * 128 + h * 32 + (tid & 31);
        scs[tid] = g_cs[jg];
        scb[tid] = g_cb[jg];
    }
    for (int p = tid; p < POSN; p += 512) {
        float a = g_pos[h * POSN + p];
        tab[2 * p] = a;
        if (p < POSN - 1) tab[2 * p + 3] = a;
    }
    if (tid == 0) tab[1] = 0.f;

    // ---- phase B: streamed GEMM1 (proj 96 cols) + LN stats ----
    float c1[12][4];
#pragma unroll
    for (int nj = 0; nj < 12; nj++) {
        c1[nj][0] = 0.f; c1[nj][1] = 0.f; c1[nj][2] = 0.f; c1[nj][3] = 0.f;
    }
    float sA[4], qA[4];
#pragma unroll
    for (int i = 0; i < 4; i++) { sA[i] = 0.f; qA[i] = 0.f; }

    for (int kt = 0; kt < 4; kt++) {
        __syncthreads();   // prev GEMM reads of x-chunk done
        // load x chunk [256 rows][32 cols] -> bf16 into FS_QS region
#pragma unroll
        for (int i = 0; i < 4; i++) {
            int f = i * 512 + tid;             // 2048 float4
            int row = f >> 3, g8 = f & 7;      // row = i*64 + (tid>>3), g8 = tid&7
            int imgrow = (b_ << 16) + (((wh << 4) + (row >> 4)) << 8) + (ww << 4) + (row & 15);
            float4 v = *(const float4*)(x + (size_t)imgrow * 128 + kt * 32 + g8 * 4);
            sA[i] += v.x + v.y + v.z + v.w;
            qA[i] += v.x * v.x + v.y * v.y + v.z * v.z + v.w * v.w;
            uint2 o;
            o.x = bf2pack(v.x, v.y);
            o.y = bf2pack(v.z, v.w);
            *(uint2*)(smc + FS_QS + row * 80 + g8 * 8) = o;
        }
        __syncthreads();
        // GEMM: warp = rows [wid*16, wid*16+16), all 96 cols
        uint32_t af[2][4];
#pragma unroll
        for (int ks = 0; ks < 2; ks++) {
            uint32_t addr = sb + FS_QS
                + (wid * 16 + (lane & 7) + ((lane >> 3) & 1) * 8) * 80
                + (ks * 16 + ((lane >> 3) >> 1) * 8) * 2;
            ldmx4(af[ks], addr);
        }
#pragma unroll
        for (int nj = 0; nj < 12; nj++) {
            uint32_t bfr[4];
            uint32_t addr = sb + FS_WB + (nj * 8 + (lane & 7)) * 272
                          + (kt * 32 + (lane >> 3) * 8) * 2;
            ldmx4(bfr, addr);
            mma16816(c1[nj], af[0], &bfr[0]);
            mma16816(c1[nj], af[1], &bfr[2]);
        }
    }

    // finalize LN stats: reduce over 8 lanes (g8 = tid&7)
#pragma unroll
    for (int i = 0; i < 4; i++) {
        float s = sA[i], q = qA[i];
#pragma unroll
        for (int o = 1; o < 8; o <<= 1) {
            s += __shfl_xor_sync(0xffffffffu, s, o);
            q += __shfl_xor_sync(0xffffffffu, q, o);
        }
        if ((tid & 7) == 0) {
            int row = i * 64 + (tid >> 3);
            float mu = s * (1.f / 128.f);
            smean[row] = mu;
            srstd[row] = rsqrtf(q * (1.f / 128.f) - mu * mu + 1e-5f);
        }
    }
    __syncthreads();   // GEMM reads of x-chunk + stats writes complete

    // ---- phase C: epilogue -> q/k/v bf16 in smem ----
    {
        int r0 = wid * 16 + (lane >> 2);
        int r1 = r0 + 8;
        float mn0 = smean[r0], mn1 = smean[r1];
        float rs0 = srstd[r0], rs1 = srstd[r1];
#pragma unroll
        for (int nj = 0; nj < 12; nj++) {
            int j0 = nj * 8 + 2 * (lane & 3);
            float2 cs2 = *(float2*)(scs + j0);
            float2 cb2 = *(float2*)(scb + j0);
            int kind = j0 >> 5, d0 = j0 & 31;
            float qsc = (kind == 0) ? (QKSCALE * LOG2E) : 1.f;
            float ia = rs0 * qsc, ib = rs1 * qsc;
            float v00 = ia * (c1[nj][0] - mn0 * cs2.x) + cb2.x;
            float v01 = ia * (c1[nj][1] - mn0 * cs2.y) + cb2.y;
            float v10 = ib * (c1[nj][2] - mn1 * cs2.x) + cb2.x;
            float v11 = ib * (c1[nj][3] - mn1 * cs2.y) + cb2.y;
            uint32_t base = (uint32_t)(FS_QS + kind * 20480);
            *(uint32_t*)(smc + base + r0 * 80 + d0 * 2) = bf2pack(v00, v01);
            *(uint32_t*)(smc + base + r1 * 80 + d0 * 2) = bf2pack(v10, v11);
        }
    }
    __syncthreads();

    // ---- phase D: attention, 16 rows/warp, 8x32-col chunks ----
    int r0 = wid * 16;
    int row0 = r0 + (lane >> 2);
    int tb0 = ((row0 >> 4) + 15) * 31 + (row0 & 15) + 15 - 2 * (lane & 3);

    uint32_t af[2][4];
#pragma unroll
    for (int kt = 0; kt < 2; kt++) {
        uint32_t addr = sb + FS_QS
            + (r0 + (lane & 7) + ((lane >> 3) & 1) * 8) * 80
            + (kt * 16 + ((lane >> 3) >> 1) * 8) * 2;
        ldmx4(af[kt], addr);
    }

    float O[4][4];
#pragma unroll
    for (int nc2 = 0; nc2 < 4; nc2++) {
        O[nc2][0] = 0.f; O[nc2][1] = 0.f; O[nc2][2] = 0.f; O[nc2][3] = 0.f;
    }
    float sum0 = 0.f, sum1 = 0.f;

#pragma unroll
    for (int chunk = 0; chunk < 8; chunk++) {
        // GEMM1': S chunk
        float S[4][4];
#pragma unroll
        for (int nc = 0; nc < 4; nc++) {
            S[nc][0] = 0.f; S[nc][1] = 0.f; S[nc][2] = 0.f; S[nc][3] = 0.f;
            uint32_t bfr[4];
            uint32_t addr = sb + FS_KS
                + ((chunk * 4 + nc) * 8 + (lane & 7)) * 80 + (lane >> 3) * 16;
            ldmx4(bfr, addr);
            mma16816(S[nc], af[0], &bfr[0]);
            mma16816(S[nc], af[1], &bfr[2]);
        }

        // bias + exp2 + pack
        uint32_t paA[4], paB[4];
#pragma unroll
        for (int nc = 0; nc < 4; nc++) {
            int g = chunk * 4 + nc;
            int t00 = tb0 - (g >> 1) * 31 - 8 * (g & 1);
            float2 b00 = *(const float2*)(tab + 2 * t00);
            float2 b08 = *(const float2*)(tab + 2 * t00 + 16);
            float e0 = ex2f(S[nc][0] + b00.x);
            float e1 = ex2f(S[nc][1] + b00.y);
            float e2 = ex2f(S[nc][2] + b08.x);
            float e3 = ex2f(S[nc][3] + b08.y);
            sum0 += e0 + e1; sum1 += e2 + e3;
            paA[nc] = bf2pack(e0, e1);
            paB[nc] = bf2pack(e2, e3);
        }

        // GEMM2 partial
        uint32_t a0[4] = {paA[0], paB[0], paA[1], paB[1]};
        uint32_t a1[4] = {paA[2], paB[2], paA[3], paB[3]};
#pragma unroll
        for (int dp = 0; dp < 2; dp++) {
            uint32_t T0[4], T1[4];
            uint32_t base = sb + FS_VS
                + (chunk * 32 + (lane & 7) + ((lane >> 3) & 1) * 8) * 80
                + (dp * 16 + ((lane >> 4) & 1) * 8) * 2;
            ldmx4t(T0, base);
            ldmx4t(T1, base + 16 * 80);
            mma16816(O[dp * 2 + 0], a0, &T0[0]);
            mma16816(O[dp * 2 + 0], a1, &T1[0]);
            mma16816(O[dp * 2 + 1], a0, &T0[2]);
            mma16816(O[dp * 2 + 1], a1, &T1[2]);
        }
    }

    // quad-reduce sums
    sum0 += __shfl_xor_sync(0xffffffffu, sum0, 1);
    sum0 += __shfl_xor_sync(0xffffffffu, sum0, 2);
    sum1 += __shfl_xor_sync(0xffffffffu, sum1, 1);
    sum1 += __shfl_xor_sync(0xffffffffu, sum1, 2);
    float inv0, inv1;
    asm("rcp.approx.ftz.f32 %0,%1;" : "=f"(inv0) : "f"(sum0));
    asm("rcp.approx.ftz.f32 %0,%1;" : "=f"(inv1) : "f"(sum1));

    // epilogue: 1/sum, residual, store
    {
        int n0 = row0;
        int n1 = row0 + 8;
        int ir0 = (b_ << 16) + (((wh << 4) + (n0 >> 4)) << 8) + (ww << 4) + (n0 & 15);
        int ir1 = (b_ << 16) + (((wh << 4) + (n1 >> 4)) << 8) + (ww << 4) + (n1 & 15);
        const float* xr0 = x + (size_t)ir0 * 128 + h * 32;
        const float* xr1 = x + (size_t)ir1 * 128 + h * 32;
        float* or0 = out + (size_t)ir0 * 128 + h * 32;
        float* or1 = out + (size_t)ir1 * 128 + h * 32;
#pragma unroll
        for (int nc2 = 0; nc2 < 4; nc2++) {
            int d0 = nc2 * 8 + 2 * (lane & 3);
            float2 xv0 = *(const float2*)(xr0 + d0);
            float2 xv1 = *(const float2*)(xr1 + d0);
            float2 o0, o1;
            o0.x = O[nc2][0] * inv0 + xv0.x;
            o0.y = O[nc2][1] * inv0 + xv0.y;
            o1.x = O[nc2][2] * inv1 + xv1.x;
            o1.y = O[nc2][3] * inv1 + xv1.y;
            *(float2*)(or0 + d0) = o0;
            *(float2*)(or1 + d0) = o1;
        }
    }
}

// ---------------- launch ----------------
extern "C" void kernel_launch(void* const* d_in, const int* in_sizes, int n_in,
                              void* d_out, int out_size)
{
    (void)in_sizes; (void)n_in; (void)out_size;
    const float* x      = (const float*)d_in[0];
    const float* n1g    = (const float*)d_in[1];
    const float* n1b    = (const float*)d_in[2];
    const float* qkv_w  = (const float*)d_in[3];
    const float* qkv_b  = (const float*)d_in[4];
    const float* pp_w   = (const float*)d_in[5];
    const float* pp_b   = (const float*)d_in[6];
    const float* l1_g   = (const float*)d_in[7];
    const float* l1_b   = (const float*)d_in[8];
    const float* f1_w   = (const float*)d_in[9];
    const float* f1_b   = (const float*)d_in[10];
    const float* l2_g   = (const float*)d_in[11];
    const float* l2_b   = (const float*)d_in[12];
    const float* f2_w   = (const float*)d_in[13];
    const float* f2_b   = (const float*)d_in[14];
    const float* l3_g   = (const float*)d_in[15];
    const float* l3_b   = (const float*)d_in[16];
    const float* f3_w   = (const float*)d_in[17];
    const float* f3_b   = (const float*)d_in[18];
    float* out = (float*)d_out;

    cudaFuncSetAttribute(fused_kernel, cudaFuncAttributeMaxDynamicSharedMemorySize, FUSED_SMEM);

    prep_pos_kernel<<<1, 1024>>>(pp_w, pp_b, l1_g, l1_b, f1_w, f1_b,
                                 l2_g, l2_b, f2_w, f2_b, l3_g, l3_b, f3_w, f3_b);
    prep_w_kernel<<<384, 128>>>(qkv_w, qkv_b, n1g, n1b);
    fused_kernel<<<2048, 512, FUSED_SMEM>>>(x, out);
}